// round 8
// baseline (speedup 1.0000x reference)
#include <cuda_runtime.h>
#include <cuda_fp16.h>

// ---------------------------------------------------------------------------
// PyramidAttention (UrbanODE core), B=32, C=64, H=W=32, 5 scales, N=3278.
//
//   S[m,q]      = sum_c refm[c,m] * match[c,q]              (K=32 GEMM, fp32)
//   logit[n,p]  = 10*invnorm[n] * sum_d S[n+d, p+d]         } strip-fused softmax
//   yn          = softmax over n (per (b,p))                } (S staged in smem)
//   T[p,m]      = sum_d yn[m+d, p+d]                        (strip-fused stencil)
//   out[c,p]    = x[c,p] + 0.25 * sum_m base[c,m] * T[p,m]  (fp16 HMMA, fp32 acc)
//
// R8: gemm1 8x4/thread (fix R7 occupancy collapse: 242 regs -> ~64);
// softmax & stencilT as 8-p strips sharing staged stencil rows via smem
// (L2 stencil traffic ~2x down each).
// ---------------------------------------------------------------------------

namespace {
constexpr int kB  = 32;
constexpr int kC  = 64;
constexpr int kC2 = 32;
constexpr int kHW = 1024;
constexpr int kN  = 3278;   // 1024+784+625+484+361
constexpr int kNS = 3280;   // padded row stride
constexpr int kNC     = 512;         // stencil n-chunk
constexpr int kSROW_W = kNC + 68;    // halo 34 each side (max diag shift 33)
constexpr int kNROWS  = 30;          // 3 qy x 10 qx rows per 8-p strip
}

// scratch (device globals: allocation-free rule)
__device__ float    g_match [(size_t)kB * kC2 * kHW];
__device__ float    g_refm  [(size_t)kB * kC2 * kN];
__device__ __half   g_base16[(size_t)kB * kC  * kN];
__device__ float    g_sq    [(size_t)kB * kN];
__device__ float    g_invn  [(size_t)kB * kN];
__device__ unsigned g_tab   [kN];                     // bits[0:9] pyr validity, bits[9:16] wl
__device__ float    g_S     [(size_t)kB * kHW * kNS]; // fp32 correlation
__device__ __half   g_yn    [(size_t)kB * kHW * kNS]; // fp16 softmax output
__device__ __half   g_T     [(size_t)kB * kHW * kNS]; // fp16 folded weights

// pyramid pixel -> (level-local y, x, level width). levels are square.
__device__ __forceinline__ void n_geom(int n, int& ny, int& nx, int& wl)
{
    if (n < 1024)      { int loc = n;        ny = loc >> 5;  nx = loc & 31;     wl = 32; }
    else if (n < 1808) { int loc = n - 1024; ny = loc / 28;  nx = loc - ny*28;  wl = 28; }
    else if (n < 2433) { int loc = n - 1808; ny = loc / 25;  nx = loc - ny*25;  wl = 25; }
    else if (n < 2917) { int loc = n - 2433; ny = loc / 22;  nx = loc - ny*22;  wl = 22; }
    else               { int loc = n - 2917; ny = loc / 19;  nx = loc - ny*19;  wl = 19; }
}

// ---------------------------------------------------------------------------
// match_base = prelu(conv1x1(x, w_base)) : [B,32,1024]
// ---------------------------------------------------------------------------
__global__ __launch_bounds__(256) void k_conv_main(
    const float* __restrict__ x, const float* __restrict__ w,
    const float* __restrict__ bias, const float* __restrict__ a)
{
    int t = blockIdx.x * blockDim.x + threadIdx.x;
    if (t >= kB * kC2 * kHW) return;
    int p  = t & (kHW - 1);
    int co = (t >> 10) & 31;
    int b  = t >> 15;
    const float* xb = x + ((size_t)b * kC) * kHW + p;
    const float* wr = w + co * kC;
    float acc = bias[co];
#pragma unroll
    for (int c = 0; c < kC; c++) acc = fmaf(wr[c], xb[(size_t)c * kHW], acc);
    float al = a[0];
    g_match[t] = acc >= 0.f ? acc : al * acc;
}

// ---------------------------------------------------------------------------
// pyramid conv1x1 + prelu (nearest-resize folded into indexing).
// DST=0 -> g_refm fp32 (also writes g_sq), DST=1 -> g_base16 fp16.
// ---------------------------------------------------------------------------
template <int COUT, int DST>
__global__ __launch_bounds__(256) void k_conv_pyr(
    const float* __restrict__ x, const float* __restrict__ w,
    const float* __restrict__ bias, const float* __restrict__ a)
{
    __shared__ float ws[COUT * kC];
    for (int i = threadIdx.x; i < COUT * kC; i += 256) ws[i] = w[i];
    __syncthreads();

    int n = blockIdx.x * 256 + threadIdx.x;
    int b = blockIdx.y;
    if (n >= kN) return;

    int ny, nx, wl;
    n_geom(n, ny, nx, wl);
    int sy = (ny * 32) / wl;
    int sx = (nx * 32) / wl;
    const float* xb = x + ((size_t)b * kC) * kHW + sy * 32 + sx;

    float acc[COUT];
#pragma unroll
    for (int co = 0; co < COUT; co++) acc[co] = bias[co];
#pragma unroll 4
    for (int c = 0; c < kC; c++) {
        float xv = xb[(size_t)c * kHW];
#pragma unroll
        for (int co = 0; co < COUT; co++) acc[co] = fmaf(ws[co * kC + c], xv, acc[co]);
    }
    float al = a[0];
    if (DST == 0) {
        float* ob = g_refm + (size_t)b * COUT * kN + n;
        float sq = 0.f;
#pragma unroll
        for (int co = 0; co < COUT; co++) {
            float v = acc[co];
            v = v >= 0.f ? v : al * v;
            ob[(size_t)co * kN] = v;
            sq = fmaf(v, v, sq);
        }
        g_sq[(size_t)b * kN + n] = sq;
    } else {
        __half* ob = g_base16 + (size_t)b * COUT * kN + n;
#pragma unroll
        for (int co = 0; co < COUT; co++) {
            float v = acc[co];
            v = v >= 0.f ? v : al * v;
            ob[(size_t)co * kN] = __float2half(v);
        }
    }
}

// invnorm[n] = 10 / max(sqrt(sum_{valid d} sq[n+d]), 1e-4); b==0 also builds g_tab
__global__ __launch_bounds__(256) void k_invn()
{
    int t = blockIdx.x * blockDim.x + threadIdx.x;
    if (t >= kB * kN) return;
    int n = t % kN, b = t / kN;
    int ny, nx, wl;
    n_geom(n, ny, nx, wl);
    const float* sq = g_sq + (size_t)b * kN;
    float s = 0.f;
    unsigned m = 0;
    int i = 0;
#pragma unroll
    for (int dy = -1; dy <= 1; dy++) {
#pragma unroll
        for (int dx = -1; dx <= 1; dx++, i++) {
            int my = ny + dy, mx = nx + dx;
            if ((unsigned)my < (unsigned)wl && (unsigned)mx < (unsigned)wl) {
                s += sq[n + dy * wl + dx];
                m |= 1u << i;
            }
        }
    }
    float nr = fmaxf(sqrtf(s), 1e-4f);
    g_invn[t] = 10.f / nr;
    if (b == 0) g_tab[n] = m | ((unsigned)wl << 9);
}

// ---------------------------------------------------------------------------
// GEMM1: S[b][p][n] = sum_{c<32} match[b][c][p] * refm[b][c][n]
// 128p x 64n tile, 8x4 per thread: 1.5 smem B/FMA, ~64 regs -> 3-4 blocks/SM.
// ---------------------------------------------------------------------------
__global__ __launch_bounds__(256) void k_gemm1()
{
    __shared__ float As[32][132];  // [k][p] (128 + pad)
    __shared__ float Bs[32][68];   // [k][n] (64 + pad)
    int b  = blockIdx.z;
    int p0 = blockIdx.y * 128;
    int n0 = blockIdx.x * 64;
    const float* Ab = g_match + (size_t)b * kC2 * kHW;
    const float* Bb = g_refm  + (size_t)b * kC2 * kN;
    int tid = threadIdx.x;
#pragma unroll
    for (int i = tid; i < 32 * 128; i += 256) {
        int k = i >> 7, j = i & 127;
        As[k][j] = Ab[(size_t)k * kHW + p0 + j];
    }
#pragma unroll
    for (int i = tid; i < 32 * 64; i += 256) {
        int k = i >> 6, j = i & 63;
        int n = n0 + j;
        Bs[k][j] = (n < kN) ? Bb[(size_t)k * kN + n] : 0.f;
    }
    __syncthreads();
    int tx = tid & 15, ty = tid >> 4;
    float acc[8][4] = {};
#pragma unroll
    for (int k = 0; k < 32; k++) {
        float av[8], bv[4];
#pragma unroll
        for (int r = 0; r < 8; r++) av[r] = As[k][ty + r * 16];
#pragma unroll
        for (int l = 0; l < 4; l++) bv[l] = Bs[k][tx + l * 16];
#pragma unroll
        for (int r = 0; r < 8; r++)
#pragma unroll
            for (int l = 0; l < 4; l++) acc[r][l] = fmaf(av[r], bv[l], acc[r][l]);
    }
    float* Sb = g_S + (size_t)b * kHW * kNS;
#pragma unroll
    for (int r = 0; r < 8; r++) {
        int p = p0 + ty + r * 16;
#pragma unroll
        for (int l = 0; l < 4; l++) {
            int n = n0 + tx + l * 16;
            if (n < kN) Sb[(size_t)p * kNS + n] = acc[r][l];
        }
    }
}

// 9-tap p-side validity mask for pixel p
__device__ __forceinline__ unsigned p_mask(int py, int px)
{
    unsigned pm = 0;
    int i = 0;
#pragma unroll
    for (int dy = -1; dy <= 1; dy++)
#pragma unroll
        for (int dx = -1; dx <= 1; dx++, i++)
            if ((unsigned)(py + dy) < 32u && (unsigned)(px + dx) < 32u) pm |= 1u << i;
    return pm;
}

// ---------------------------------------------------------------------------
// STRIP-FUSED softmax: block = 8 consecutive p's (same py). S rows needed by
// the 8 stencils (3x10 q-grid) are staged chunk-wise into smem (+34 halo);
// logits built from smem, then per-p softmax, yn written fp16.
// dynamic smem: logit[8*kNS] | srow[30*kSROW_W] | tabs[kNC] | invns[kNC]
// ---------------------------------------------------------------------------
__global__ __launch_bounds__(512) void k_softmax()
{
    extern __shared__ float dyn[];
    float*    logit = dyn;                       // 8*kNS
    float*    srow  = dyn + 8 * kNS;             // kNROWS*kSROW_W
    unsigned* tabs  = (unsigned*)(srow + kNROWS * kSROW_W);
    float*    invns = (float*)(tabs + kNC);
    __shared__ float red[32];

    int b = blockIdx.y, strip = blockIdx.x;
    int py  = strip >> 2;
    int px0 = (strip & 3) << 3;
    int tid = threadIdx.x;
    int lane = tid & 31, wid = tid >> 5;

    const float* S = g_S + (size_t)b * kHW * kNS;
    unsigned pm[8];
#pragma unroll
    for (int j = 0; j < 8; j++) pm[j] = p_mask(py, px0 + j);

    float mx8[8];
#pragma unroll
    for (int j = 0; j < 8; j++) mx8[j] = -3.4e38f;

    constexpr int NCH = (kNS + kNC - 1) / kNC;   // 7
    for (int ch = 0; ch < NCH; ch++) {
        int n0 = ch * kNC;
        __syncthreads();
        // stage S rows (invalid rows / out-of-range cols -> 0)
        for (int i = tid; i < kNROWS * kSROW_W; i += 512) {
            int r = i / kSROW_W, cc = i - r * kSROW_W;
            int qy = py - 1 + r / 10;
            int qx = px0 - 1 + (r - (r / 10) * 10);
            int c = n0 - 34 + cc;
            float v = 0.f;
            if ((unsigned)qy < 32u && (unsigned)qx < 32u && (unsigned)c < (unsigned)kNS)
                v = S[(size_t)(qy * 32 + qx) * kNS + c];
            srow[i] = v;
        }
        for (int i = tid; i < kNC; i += 512) {
            int n = n0 + i;
            tabs[i]  = (n < kN) ? g_tab[n] : 0u;
            invns[i] = (n < kN) ? g_invn[(size_t)b * kN + n] : 0.f;
        }
        __syncthreads();
        int n = n0 + tid;
        if (n < kN) {
            unsigned tb = tabs[tid];
            int wl = (int)(tb >> 9);
            int off[9] = {-wl - 1, -wl, -wl + 1, -1, 0, 1, wl - 1, wl, wl + 1};
            int scb = tid + 34;
            float iv = invns[tid];
#pragma unroll
            for (int j = 0; j < 8; j++) {
                unsigned m = tb & pm[j];
                float s = 0.f;
#pragma unroll
                for (int i = 0; i < 9; i++) {
                    if ((m >> i) & 1u) {
                        int r = (i / 3) * 10 + (i % 3) + j;
                        s += srow[r * kSROW_W + scb + off[i]];
                    }
                }
                s *= iv;
                logit[j * kNS + n] = s;
                mx8[j] = fmaxf(mx8[j], s);
            }
        }
    }
    __syncthreads();

    // per-p softmax over the smem logit rows
    for (int j = 0; j < 8; j++) {
        float mx = mx8[j];
#pragma unroll
        for (int o = 16; o; o >>= 1) mx = fmaxf(mx, __shfl_xor_sync(0xffffffffu, mx, o));
        if (lane == 0) red[wid] = mx;
        __syncthreads();
        if (tid < 32) {
            float v = (tid < 16) ? red[tid] : -3.4e38f;
#pragma unroll
            for (int o = 8; o; o >>= 1) v = fmaxf(v, __shfl_xor_sync(0xffffffffu, v, o));
            if (tid == 0) red[16] = v;
        }
        __syncthreads();
        mx = red[16];
        float sum = 0.f;
        for (int n = tid; n < kN; n += 512) {
            float e = __expf(logit[j * kNS + n] - mx);
            logit[j * kNS + n] = e;
            sum += e;
        }
#pragma unroll
        for (int o = 16; o; o >>= 1) sum += __shfl_xor_sync(0xffffffffu, sum, o);
        __syncthreads();
        if (lane == 0) red[wid] = sum;
        __syncthreads();
        if (tid < 32) {
            float v = (tid < 16) ? red[tid] : 0.f;
#pragma unroll
            for (int o = 8; o; o >>= 1) v += __shfl_xor_sync(0xffffffffu, v, o);
            if (tid == 0) red[16] = v;
        }
        __syncthreads();
        float inv = 1.f / red[16];
        __half* yn = g_yn + ((size_t)b * kHW + py * 32 + px0 + j) * kNS;
        for (int n = tid; n < kN; n += 512) yn[n] = __float2half(logit[j * kNS + n] * inv);
        __syncthreads();
    }
}

// ---------------------------------------------------------------------------
// STRIP-FUSED T stencil: same staging pattern over fp16 yn; no reductions.
// ---------------------------------------------------------------------------
__global__ __launch_bounds__(512) void k_stencilT()
{
    __shared__ __half  srow[kNROWS * kSROW_W];   // 34.8 KB
    __shared__ unsigned tabs[kNC];
    int b = blockIdx.y, strip = blockIdx.x;
    int py  = strip >> 2;
    int px0 = (strip & 3) << 3;
    int tid = threadIdx.x;

    const __half* Y = g_yn + (size_t)b * kHW * kNS;
    unsigned pm[8];
#pragma unroll
    for (int j = 0; j < 8; j++) pm[j] = p_mask(py, px0 + j);

    constexpr int NCH = (kNS + kNC - 1) / kNC;
    for (int ch = 0; ch < NCH; ch++) {
        int n0 = ch * kNC;
        __syncthreads();
        for (int i = tid; i < kNROWS * kSROW_W; i += 512) {
            int r = i / kSROW_W, cc = i - r * kSROW_W;
            int qy = py - 1 + r / 10;
            int qx = px0 - 1 + (r - (r / 10) * 10);
            int c = n0 - 34 + cc;
            __half v = __float2half(0.f);
            if ((unsigned)qy < 32u && (unsigned)qx < 32u && (unsigned)c < (unsigned)kNS)
                v = Y[(size_t)(qy * 32 + qx) * kNS + c];
            srow[i] = v;
        }
        for (int i = tid; i < kNC; i += 512) {
            int n = n0 + i;
            tabs[i] = (n < kN) ? g_tab[n] : 0u;
        }
        __syncthreads();
        int n = n0 + tid;
        if (n < kN) {
            unsigned tb = tabs[tid];
            int wl = (int)(tb >> 9);
            int off[9] = {-wl - 1, -wl, -wl + 1, -1, 0, 1, wl - 1, wl, wl + 1};
            int scb = tid + 34;
#pragma unroll
            for (int j = 0; j < 8; j++) {
                unsigned m = tb & pm[j];
                float s = 0.f;
#pragma unroll
                for (int i = 0; i < 9; i++) {
                    if ((m >> i) & 1u)
                        s += __half2float(srow[(size_t)((i / 3) * 10 + (i % 3) + j) * kSROW_W + scb + off[i]]);
                }
                g_T[((size_t)b * kHW + py * 32 + px0 + j) * kNS + n] = __float2half(s);
            }
        }
    }
}

// ---------------------------------------------------------------------------
// GEMM2 on tensor cores: out[b][c][p] = x[b][c][p] + 0.25*sum_m base*T
// Block tile 64c x 128p, BK=64. 8 warps 2(c)x4(p); m16n8k16 HMMA fp32 acc.
// ---------------------------------------------------------------------------
__global__ __launch_bounds__(256) void k_gemm2(
    const float* __restrict__ x, float* __restrict__ out)
{
    constexpr int BK = 64;
    constexpr int SA = 72;
    __shared__ __half As[64 * SA];
    __shared__ __half Bs[128 * SA];
    int b  = blockIdx.y;
    int p0 = blockIdx.x * 128;
    const __half* Ab = g_base16 + (size_t)b * kC * kN;
    const __half* Tb = g_T      + (size_t)b * kHW * kNS;
    int tid  = threadIdx.x;
    int lane = tid & 31, warp = tid >> 5;
    int wc = (warp & 1) * 32;
    int wp = (warp >> 1) * 32;
    int gid = lane >> 2, tig = lane & 3;
    float acc[2][4][4] = {};

    for (int k0 = 0; k0 < kN; k0 += BK) {
#pragma unroll
        for (int j = 0; j < 8; j++) {
            int idx = tid + j * 256;
            int c = idx >> 5, kk = (idx & 31) * 2;
            int k = k0 + kk;
            unsigned v = 0;
            if (k < kN) v = *(const unsigned*)(Ab + (size_t)c * kN + k);
            *(unsigned*)(&As[c * SA + kk]) = v;
        }
#pragma unroll
        for (int j = 0; j < 16; j++) {
            int idx = tid + j * 256;
            int pp = idx >> 5, kk = (idx & 31) * 2;
            int k = k0 + kk;
            unsigned v = 0;
            if (k < kN) v = *(const unsigned*)(Tb + (size_t)(p0 + pp) * kNS + k);
            *(unsigned*)(&Bs[pp * SA + kk]) = v;
        }
        __syncthreads();
#pragma unroll
        for (int ks = 0; ks < 4; ks++) {
            int kb = ks * 16;
            unsigned a[2][4], bf[4][2];
#pragma unroll
            for (int mt = 0; mt < 2; mt++) {
                const __half* ap = &As[(wc + mt * 16 + gid) * SA + kb + tig * 2];
                a[mt][0] = *(const unsigned*)(ap);
                a[mt][1] = *(const unsigned*)(ap + 8 * SA);
                a[mt][2] = *(const unsigned*)(ap + 8);
                a[mt][3] = *(const unsigned*)(ap + 8 * SA + 8);
            }
#pragma unroll
            for (int nt = 0; nt < 4; nt++) {
                const __half* bp = &Bs[(wp + nt * 8 + gid) * SA + kb + tig * 2];
                bf[nt][0] = *(const unsigned*)(bp);
                bf[nt][1] = *(const unsigned*)(bp + 8);
            }
#pragma unroll
            for (int mt = 0; mt < 2; mt++)
#pragma unroll
                for (int nt = 0; nt < 4; nt++) {
                    asm volatile(
                        "mma.sync.aligned.m16n8k16.row.col.f32.f16.f16.f32 "
                        "{%0,%1,%2,%3}, {%4,%5,%6,%7}, {%8,%9}, {%0,%1,%2,%3};"
                        : "+f"(acc[mt][nt][0]), "+f"(acc[mt][nt][1]),
                          "+f"(acc[mt][nt][2]), "+f"(acc[mt][nt][3])
                        : "r"(a[mt][0]), "r"(a[mt][1]), "r"(a[mt][2]), "r"(a[mt][3]),
                          "r"(bf[nt][0]), "r"(bf[nt][1]));
                }
        }
        __syncthreads();
    }

    const float* xb = x   + (size_t)b * kC * kHW;
    float*       ob = out + (size_t)b * kC * kHW;
#pragma unroll
    for (int mt = 0; mt < 2; mt++) {
        int c = wc + mt * 16 + gid;
#pragma unroll
        for (int nt = 0; nt < 4; nt++) {
            int pc = p0 + wp + nt * 8 + tig * 2;
            ob[(size_t)c * kHW + pc]           = fmaf(0.25f, acc[mt][nt][0], xb[(size_t)c * kHW + pc]);
            ob[(size_t)c * kHW + pc + 1]       = fmaf(0.25f, acc[mt][nt][1], xb[(size_t)c * kHW + pc + 1]);
            ob[(size_t)(c + 8) * kHW + pc]     = fmaf(0.25f, acc[mt][nt][2], xb[(size_t)(c + 8) * kHW + pc]);
            ob[(size_t)(c + 8) * kHW + pc + 1] = fmaf(0.25f, acc[mt][nt][3], xb[(size_t)(c + 8) * kHW + pc + 1]);
        }
    }
}

// ---------------------------------------------------------------------------
extern "C" void kernel_launch(void* const* d_in, const int* in_sizes, int n_in,
                              void* d_out, int out_size)
{
    (void)in_sizes; (void)n_in; (void)out_size;
    const float* x       = (const float*)d_in[0];
    const float* w_base  = (const float*)d_in[1];
    const float* b_base  = (const float*)d_in[2];
    const float* a_base  = (const float*)d_in[3];
    const float* w_match = (const float*)d_in[4];
    const float* b_match = (const float*)d_in[5];
    const float* a_match = (const float*)d_in[6];
    const float* w_asm   = (const float*)d_in[7];
    const float* b_asm   = (const float*)d_in[8];
    const float* a_asm   = (const float*)d_in[9];
    float* out = (float*)d_out;

    // dynamic smem for the strip softmax: logit + staged rows + tabs/invn
    constexpr int kSoftSmem =
        (8 * kNS + kNROWS * kSROW_W + 2 * kNC) * 4;
    static bool attr_done = false;
    if (!attr_done) {
        cudaFuncSetAttribute(k_softmax, cudaFuncAttributeMaxDynamicSharedMemorySize, kSoftSmem);
        attr_done = true;
    }

    k_conv_main<<<(kB * kC2 * kHW + 255) / 256, 256>>>(x, w_base, b_base, a_base);
    {
        dim3 g((kN + 255) / 256, kB);
        k_conv_pyr<kC2, 0><<<g, 256>>>(x, w_match, b_match, a_match);  // -> g_refm, g_sq
        k_conv_pyr<kC,  1><<<g, 256>>>(x, w_asm,   b_asm,   a_asm);    // -> g_base16
    }
    {
        dim3 g((kN + 63) / 64, kHW / 128, kB);
        k_gemm1<<<g, 256>>>();                                          // 4th launch (profiled)
    }
    k_invn<<<(kB * kN + 255) / 256, 256>>>();                           // also builds g_tab
    {
        dim3 g(128, kB);
        k_softmax<<<g, 512, kSoftSmem>>>();
        k_stencilT<<<g, 512>>>();
    }
    {
        dim3 g(kHW / 128, kB);
        k_gemm2<<<g, 256>>>(x, out);
    }
}

// round 9
// speedup vs baseline: 1.4495x; 1.4495x over previous
#include <cuda_runtime.h>
#include <cuda_fp16.h>

// ---------------------------------------------------------------------------
// PyramidAttention (UrbanODE core), B=32, C=64, H=W=32, 5 scales, N=3278.
//
//   S[m,q]      = sum_c refm[c,m] * match[c,q]              (K=32 GEMM, fp32)
//   logit[n,p]  = 10*invnorm[n] * sum_d S[n+d, p+d]         } fused softmax:
//   e           = exp(logit - max), inv[p] = 1/sum e        } e fp16 + inv
//   T[p,m]      = sum_d inv[p+d] * e[p+d][m+d]              (stencil w/ inv)
//   out[c,p]    = x[c,p] + 0.25 * sum_m base[c,m] * T[p,m]  (fp16 HMMA, fp32 acc)
//
// R9: revert R8 strips (occupancy collapse). R8 gemm1 kept. Normalization
// deferred into stencilT; invn folded into softmax (sq row staged in smem);
// pyramid convs merged. Softmax sits in the profiled 4th launch slot.
// ---------------------------------------------------------------------------

namespace {
constexpr int kB  = 32;
constexpr int kC  = 64;
constexpr int kC2 = 32;
constexpr int kHW = 1024;
constexpr int kN  = 3278;   // 1024+784+625+484+361
constexpr int kNS = 3280;   // padded row stride
}

// scratch (device globals: allocation-free rule)
__device__ float    g_match [(size_t)kB * kC2 * kHW];
__device__ float    g_refm  [(size_t)kB * kC2 * kN];
__device__ __half   g_base16[(size_t)kB * kC  * kN];
__device__ float    g_sq    [(size_t)kB * kN];
__device__ float    g_inv   [(size_t)kB * kHW];      // per-(b,p) 1/sum(e)
__device__ unsigned g_tab   [kN];                    // bits[0:9] pyr validity, bits[9:16] wl
__device__ float    g_S     [(size_t)kB * kHW * kNS]; // fp32 correlation
__device__ __half   g_e     [(size_t)kB * kHW * kNS]; // fp16 exp(logit-max)
__device__ __half   g_T     [(size_t)kB * kHW * kNS]; // fp16 folded weights

// pyramid pixel -> (level-local y, x, level width). levels are square.
__device__ __forceinline__ void n_geom(int n, int& ny, int& nx, int& wl)
{
    if (n < 1024)      { int loc = n;        ny = loc >> 5;  nx = loc & 31;     wl = 32; }
    else if (n < 1808) { int loc = n - 1024; ny = loc / 28;  nx = loc - ny*28;  wl = 28; }
    else if (n < 2433) { int loc = n - 1808; ny = loc / 25;  nx = loc - ny*25;  wl = 25; }
    else if (n < 2917) { int loc = n - 2433; ny = loc / 22;  nx = loc - ny*22;  wl = 22; }
    else               { int loc = n - 2917; ny = loc / 19;  nx = loc - ny*19;  wl = 19; }
}

// ---------------------------------------------------------------------------
// match_base = prelu(conv1x1(x, w_base)) : [B,32,1024]
// ---------------------------------------------------------------------------
__global__ __launch_bounds__(256) void k_conv_main(
    const float* __restrict__ x, const float* __restrict__ w,
    const float* __restrict__ bias, const float* __restrict__ a)
{
    int t = blockIdx.x * blockDim.x + threadIdx.x;
    if (t >= kB * kC2 * kHW) return;
    int p  = t & (kHW - 1);
    int co = (t >> 10) & 31;
    int b  = t >> 15;
    const float* xb = x + ((size_t)b * kC) * kHW + p;
    const float* wr = w + co * kC;
    float acc = bias[co];
#pragma unroll
    for (int c = 0; c < kC; c++) acc = fmaf(wr[c], xb[(size_t)c * kHW], acc);
    float al = a[0];
    g_match[t] = acc >= 0.f ? acc : al * acc;
}

// ---------------------------------------------------------------------------
// BOTH pyramid conv1x1+prelu projections in one pass (x row loaded once):
// refm (32ch fp32 + sq) and base (64ch fp16). Also builds g_tab on b==0.
// ---------------------------------------------------------------------------
__global__ __launch_bounds__(256) void k_conv_pyr(
    const float* __restrict__ x,
    const float* __restrict__ w_match, const float* __restrict__ b_match,
    const float* __restrict__ a_match,
    const float* __restrict__ w_asm, const float* __restrict__ b_asm,
    const float* __restrict__ a_asm)
{
    __shared__ float wsM[kC2 * kC];
    __shared__ float wsA[kC * kC];
    for (int i = threadIdx.x; i < kC2 * kC; i += 256) wsM[i] = w_match[i];
    for (int i = threadIdx.x; i < kC * kC; i += 256)  wsA[i] = w_asm[i];
    __syncthreads();

    int n = blockIdx.x * 256 + threadIdx.x;
    int b = blockIdx.y;
    if (n >= kN) return;

    int ny, nx, wl;
    n_geom(n, ny, nx, wl);
    int sy = (ny * 32) / wl;
    int sx = (nx * 32) / wl;
    const float* xb = x + ((size_t)b * kC) * kHW + sy * 32 + sx;

    float accM[kC2], accA[kC];
#pragma unroll
    for (int co = 0; co < kC2; co++) accM[co] = b_match[co];
#pragma unroll
    for (int co = 0; co < kC; co++)  accA[co] = b_asm[co];
#pragma unroll 2
    for (int c = 0; c < kC; c++) {
        float xv = xb[(size_t)c * kHW];
#pragma unroll
        for (int co = 0; co < kC2; co++) accM[co] = fmaf(wsM[co * kC + c], xv, accM[co]);
#pragma unroll
        for (int co = 0; co < kC; co++)  accA[co] = fmaf(wsA[co * kC + c], xv, accA[co]);
    }
    float alM = a_match[0], alA = a_asm[0];
    float* obM = g_refm + (size_t)b * kC2 * kN + n;
    float sq = 0.f;
#pragma unroll
    for (int co = 0; co < kC2; co++) {
        float v = accM[co];
        v = v >= 0.f ? v : alM * v;
        obM[(size_t)co * kN] = v;
        sq = fmaf(v, v, sq);
    }
    g_sq[(size_t)b * kN + n] = sq;

    __half* obA = g_base16 + (size_t)b * kC * kN + n;
#pragma unroll
    for (int co = 0; co < kC; co++) {
        float v = accA[co];
        v = v >= 0.f ? v : alA * v;
        obA[(size_t)co * kN] = __float2half(v);
    }

    if (b == 0) {
        unsigned m = 0;
        int i = 0;
#pragma unroll
        for (int dy = -1; dy <= 1; dy++)
#pragma unroll
            for (int dx = -1; dx <= 1; dx++, i++)
                if ((unsigned)(ny + dy) < (unsigned)wl && (unsigned)(nx + dx) < (unsigned)wl)
                    m |= 1u << i;
        g_tab[n] = m | ((unsigned)wl << 9);
    }
}

// ---------------------------------------------------------------------------
// GEMM1: S[b][p][n] = sum_{c<32} match[b][c][p] * refm[b][c][n]
// 128p x 64n tile, 8x4 per thread (R8-measured: 232us, occ 60%).
// ---------------------------------------------------------------------------
__global__ __launch_bounds__(256) void k_gemm1()
{
    __shared__ float As[32][132];
    __shared__ float Bs[32][68];
    int b  = blockIdx.z;
    int p0 = blockIdx.y * 128;
    int n0 = blockIdx.x * 64;
    const float* Ab = g_match + (size_t)b * kC2 * kHW;
    const float* Bb = g_refm  + (size_t)b * kC2 * kN;
    int tid = threadIdx.x;
#pragma unroll
    for (int i = tid; i < 32 * 128; i += 256) {
        int k = i >> 7, j = i & 127;
        As[k][j] = Ab[(size_t)k * kHW + p0 + j];
    }
#pragma unroll
    for (int i = tid; i < 32 * 64; i += 256) {
        int k = i >> 6, j = i & 63;
        int n = n0 + j;
        Bs[k][j] = (n < kN) ? Bb[(size_t)k * kN + n] : 0.f;
    }
    __syncthreads();
    int tx = tid & 15, ty = tid >> 4;
    float acc[8][4] = {};
#pragma unroll
    for (int k = 0; k < 32; k++) {
        float av[8], bv[4];
#pragma unroll
        for (int r = 0; r < 8; r++) av[r] = As[k][ty + r * 16];
#pragma unroll
        for (int l = 0; l < 4; l++) bv[l] = Bs[k][tx + l * 16];
#pragma unroll
        for (int r = 0; r < 8; r++)
#pragma unroll
            for (int l = 0; l < 4; l++) acc[r][l] = fmaf(av[r], bv[l], acc[r][l]);
    }
    float* Sb = g_S + (size_t)b * kHW * kNS;
#pragma unroll
    for (int r = 0; r < 8; r++) {
        int p = p0 + ty + r * 16;
#pragma unroll
        for (int l = 0; l < 4; l++) {
            int n = n0 + tx + l * 16;
            if (n < kN) Sb[(size_t)p * kNS + n] = acc[r][l];
        }
    }
}

// 9-tap p-side validity mask + q-row indices
__device__ __forceinline__ unsigned p_taps(int p, int* qrow)
{
    int py = p >> 5, px = p & 31;
    unsigned pm = 0;
    int i = 0;
#pragma unroll
    for (int dy = -1; dy <= 1; dy++)
#pragma unroll
        for (int dx = -1; dx <= 1; dx++, i++) {
            int qy = py + dy, qx = px + dx;
            qrow[i] = qy * 32 + qx;
            if ((unsigned)qy < 32u && (unsigned)qx < 32u) pm |= 1u << i;
        }
    return pm;
}

// ---------------------------------------------------------------------------
// FUSED softmax: 9-tap stencil of S * invnorm (computed inline from staged sq
// row), row max, e=exp(logit-max) -> g_e (fp16), inv[p]=1/sum -> g_inv.
// One block per (p, b); normalization deferred to the T stencil.
// ---------------------------------------------------------------------------
__global__ __launch_bounds__(256) void k_softmax()
{
    __shared__ float row[kNS];
    __shared__ float sqrow[kNS];
    __shared__ float red[8];
    int p = blockIdx.x, b = blockIdx.y;
    int tid = threadIdx.x;
    int lane = tid & 31, wid = tid >> 5;
    const float* S = g_S + (size_t)b * kHW * kNS;

    // stage sq row
    {
        const float* sqg = g_sq + (size_t)b * kN;
        for (int n = tid; n < kNS; n += 256) sqrow[n] = (n < kN) ? sqg[n] : 0.f;
    }
    __syncthreads();

    int qrow[9];
    unsigned pm = p_taps(p, qrow);

    float mx = -3.4e38f;
    for (int n = tid; n < kN; n += 256) {
        unsigned tb = g_tab[n];
        int wl = (int)(tb >> 9);
        int off[9] = {-wl - 1, -wl, -wl + 1, -1, 0, 1, wl - 1, wl, wl + 1};
        // invnorm from sq row (pyramid-validity mask only)
        float nsum = 0.f;
#pragma unroll
        for (int i = 0; i < 9; i++)
            if ((tb >> i) & 1u) nsum += sqrow[n + off[i]];
        float iv = (nsum > 1e-8f) ? 10.f * rsqrtf(nsum) : 1e5f;
        // logit stencil
        unsigned m = tb & pm;
        float s = 0.f;
#pragma unroll
        for (int i = 0; i < 9; i++)
            if ((m >> i) & 1u) s += S[(size_t)qrow[i] * kNS + n + off[i]];
        s *= iv;
        row[n] = s;
        mx = fmaxf(mx, s);
    }
#pragma unroll
    for (int o = 16; o; o >>= 1) mx = fmaxf(mx, __shfl_xor_sync(0xffffffffu, mx, o));
    if (lane == 0) red[wid] = mx;
    __syncthreads();
    mx = red[0];
#pragma unroll
    for (int i = 1; i < 8; i++) mx = fmaxf(mx, red[i]);
    __syncthreads();

    float sum = 0.f;
    __half* eo = g_e + ((size_t)b * kHW + p) * kNS;
    for (int n = tid; n < kN; n += 256) {
        float e = __expf(row[n] - mx);
        eo[n] = __float2half(e);
        sum += e;
    }
#pragma unroll
    for (int o = 16; o; o >>= 1) sum += __shfl_xor_sync(0xffffffffu, sum, o);
    if (lane == 0) red[wid] = sum;
    __syncthreads();
    if (tid == 0) {
        float s = red[0];
#pragma unroll
        for (int i = 1; i < 8; i++) s += red[i];
        g_inv[(size_t)b * kHW + p] = 1.f / s;
    }
}

// ---------------------------------------------------------------------------
// T[b][p][m] = sum_{valid d} inv[p+d] * e[b][p+d][m+d]   (fp16 in/out)
// ---------------------------------------------------------------------------
__global__ __launch_bounds__(256) void k_stencilT()
{
    int n = blockIdx.x * 256 + threadIdx.x;
    if (n >= kN) return;
    int p = blockIdx.y, b = blockIdx.z;
    const __half* E = g_e + (size_t)b * kHW * kNS;

    int qrow[9];
    unsigned pm = p_taps(p, qrow);
    float ivs[9];
#pragma unroll
    for (int i = 0; i < 9; i++)
        ivs[i] = ((pm >> i) & 1u) ? g_inv[(size_t)b * kHW + qrow[i]] : 0.f;

    unsigned tb = g_tab[n];
    int wl = (int)(tb >> 9);
    unsigned m = tb & pm;
    int off[9] = {-wl - 1, -wl, -wl + 1, -1, 0, 1, wl - 1, wl, wl + 1};
    float s = 0.f;
#pragma unroll
    for (int i = 0; i < 9; i++)
        if ((m >> i) & 1u)
            s = fmaf(ivs[i], __half2float(E[(size_t)qrow[i] * kNS + n + off[i]]), s);
    g_T[((size_t)b * kHW + p) * kNS + n] = __float2half(s);
}

// ---------------------------------------------------------------------------
// GEMM2 on tensor cores: out[b][c][p] = x[b][c][p] + 0.25*sum_m base*T
// Block tile 64c x 128p, BK=64. 8 warps 2(c)x4(p); m16n8k16 HMMA fp32 acc.
// ---------------------------------------------------------------------------
__global__ __launch_bounds__(256) void k_gemm2(
    const float* __restrict__ x, float* __restrict__ out)
{
    constexpr int BK = 64;
    constexpr int SA = 72;
    __shared__ __half As[64 * SA];
    __shared__ __half Bs[128 * SA];
    int b  = blockIdx.y;
    int p0 = blockIdx.x * 128;
    const __half* Ab = g_base16 + (size_t)b * kC * kN;
    const __half* Tb = g_T      + (size_t)b * kHW * kNS;
    int tid  = threadIdx.x;
    int lane = tid & 31, warp = tid >> 5;
    int wc = (warp & 1) * 32;
    int wp = (warp >> 1) * 32;
    int gid = lane >> 2, tig = lane & 3;
    float acc[2][4][4] = {};

    for (int k0 = 0; k0 < kN; k0 += BK) {
#pragma unroll
        for (int j = 0; j < 8; j++) {
            int idx = tid + j * 256;
            int c = idx >> 5, kk = (idx & 31) * 2;
            int k = k0 + kk;
            unsigned v = 0;
            if (k < kN) v = *(const unsigned*)(Ab + (size_t)c * kN + k);
            *(unsigned*)(&As[c * SA + kk]) = v;
        }
#pragma unroll
        for (int j = 0; j < 16; j++) {
            int idx = tid + j * 256;
            int pp = idx >> 5, kk = (idx & 31) * 2;
            int k = k0 + kk;
            unsigned v = 0;
            if (k < kN) v = *(const unsigned*)(Tb + (size_t)(p0 + pp) * kNS + k);
            *(unsigned*)(&Bs[pp * SA + kk]) = v;
        }
        __syncthreads();
#pragma unroll
        for (int ks = 0; ks < 4; ks++) {
            int kb = ks * 16;
            unsigned a[2][4], bf[4][2];
#pragma unroll
            for (int mt = 0; mt < 2; mt++) {
                const __half* ap = &As[(wc + mt * 16 + gid) * SA + kb + tig * 2];
                a[mt][0] = *(const unsigned*)(ap);
                a[mt][1] = *(const unsigned*)(ap + 8 * SA);
                a[mt][2] = *(const unsigned*)(ap + 8);
                a[mt][3] = *(const unsigned*)(ap + 8 * SA + 8);
            }
#pragma unroll
            for (int nt = 0; nt < 4; nt++) {
                const __half* bp = &Bs[(wp + nt * 8 + gid) * SA + kb + tig * 2];
                bf[nt][0] = *(const unsigned*)(bp);
                bf[nt][1] = *(const unsigned*)(bp + 8);
            }
#pragma unroll
            for (int mt = 0; mt < 2; mt++)
#pragma unroll
                for (int nt = 0; nt < 4; nt++) {
                    asm volatile(
                        "mma.sync.aligned.m16n8k16.row.col.f32.f16.f16.f32 "
                        "{%0,%1,%2,%3}, {%4,%5,%6,%7}, {%8,%9}, {%0,%1,%2,%3};"
                        : "+f"(acc[mt][nt][0]), "+f"(acc[mt][nt][1]),
                          "+f"(acc[mt][nt][2]), "+f"(acc[mt][nt][3])
                        : "r"(a[mt][0]), "r"(a[mt][1]), "r"(a[mt][2]), "r"(a[mt][3]),
                          "r"(bf[nt][0]), "r"(bf[nt][1]));
                }
        }
        __syncthreads();
    }

    const float* xb = x   + (size_t)b * kC * kHW;
    float*       ob = out + (size_t)b * kC * kHW;
#pragma unroll
    for (int mt = 0; mt < 2; mt++) {
        int c = wc + mt * 16 + gid;
#pragma unroll
        for (int nt = 0; nt < 4; nt++) {
            int pc = p0 + wp + nt * 8 + tig * 2;
            ob[(size_t)c * kHW + pc]           = fmaf(0.25f, acc[mt][nt][0], xb[(size_t)c * kHW + pc]);
            ob[(size_t)c * kHW + pc + 1]       = fmaf(0.25f, acc[mt][nt][1], xb[(size_t)c * kHW + pc + 1]);
            ob[(size_t)(c + 8) * kHW + pc]     = fmaf(0.25f, acc[mt][nt][2], xb[(size_t)(c + 8) * kHW + pc]);
            ob[(size_t)(c + 8) * kHW + pc + 1] = fmaf(0.25f, acc[mt][nt][3], xb[(size_t)(c + 8) * kHW + pc + 1]);
        }
    }
}

// ---------------------------------------------------------------------------
extern "C" void kernel_launch(void* const* d_in, const int* in_sizes, int n_in,
                              void* d_out, int out_size)
{
    (void)in_sizes; (void)n_in; (void)out_size;
    const float* x       = (const float*)d_in[0];
    const float* w_base  = (const float*)d_in[1];
    const float* b_base  = (const float*)d_in[2];
    const float* a_base  = (const float*)d_in[3];
    const float* w_match = (const float*)d_in[4];
    const float* b_match = (const float*)d_in[5];
    const float* a_match = (const float*)d_in[6];
    const float* w_asm   = (const float*)d_in[7];
    const float* b_asm   = (const float*)d_in[8];
    const float* a_asm   = (const float*)d_in[9];
    float* out = (float*)d_out;

    k_conv_main<<<(kB * kC2 * kHW + 255) / 256, 256>>>(x, w_base, b_base, a_base);  // 1
    {
        dim3 g((kN + 255) / 256, kB);
        k_conv_pyr<<<g, 256>>>(x, w_match, b_match, a_match, w_asm, b_asm, a_asm);  // 2
    }
    {
        dim3 g((kN + 63) / 64, kHW / 128, kB);
        k_gemm1<<<g, 256>>>();                                                      // 3
    }
    {
        dim3 g(kHW, kB);
        k_softmax<<<g, 256>>>();                                                    // 4 (profiled)
    }
    {
        dim3 g((kN + 255) / 256, kHW, kB);
        k_stencilT<<<g, 256>>>();                                                   // 5
    }
    {
        dim3 g(kHW / 128, kB);
        k_gemm2<<<g, 256>>>(x, out);                                                // 6
    }
}